// round 2
// baseline (speedup 1.0000x reference)
#include <cuda_runtime.h>
#include <math.h>

#define BB 4
#define TT 4096
#define DD 64

// Scratch (device globals — allocation-free contract)
__device__ float  g_enc[(size_t)BB * TT * DD];        // 4 MB
__device__ float  g_scores[(size_t)BB * TT * TT];     // 268 MB
__device__ float2 g_stats[(size_t)BB * TT];           // per-(b,j): {rowmax, 1/Z}

// ---------------------------------------------------------------------------
// K1: encoded = tanh(softmax(x@W1 + b1) @ W2 + b2)   one 64-thread block/token
// ---------------------------------------------------------------------------
__global__ void k_encode(const float* __restrict__ x,
                         const float* __restrict__ W1, const float* __restrict__ b1,
                         const float* __restrict__ W2, const float* __restrict__ b2) {
    int token = blockIdx.x;
    int t = threadIdx.x;                 // 0..63 = output feature
    __shared__ float xs[64];
    __shared__ float red[64];
    __shared__ float hs[64];

    xs[t] = x[(size_t)token * 64 + t];
    __syncthreads();

    float acc = b1[t];
#pragma unroll
    for (int d = 0; d < 64; d++) acc = fmaf(xs[d], W1[d * 64 + t], acc);

    // softmax over the 64 features
    red[t] = acc; __syncthreads();
#pragma unroll
    for (int s = 32; s > 0; s >>= 1) {
        if (t < s) red[t] = fmaxf(red[t], red[t + s]);
        __syncthreads();
    }
    float m = red[0];
    __syncthreads();
    float e = expf(acc - m);
    red[t] = e; __syncthreads();
#pragma unroll
    for (int s = 32; s > 0; s >>= 1) {
        if (t < s) red[t] = red[t] + red[t + s];
        __syncthreads();
    }
    float h = e / red[0];
    hs[t] = h;
    __syncthreads();

    float acc2 = b2[t];
#pragma unroll
    for (int d = 0; d < 64; d++) acc2 = fmaf(hs[d], W2[d * 64 + t], acc2);

    g_enc[(size_t)token * 64 + t] = tanhf(acc2);
}

// ---------------------------------------------------------------------------
// K2: scores[b,i,j] = <x[b,i,:], enc[b,j,:]>      128x128 tile, K=64 one-shot
// k-major shared with XOR swizzle -> conflict-free LDS.128 in the hot loop
// ---------------------------------------------------------------------------
__device__ __forceinline__ int swz(int k, int col) {
    return col ^ ((((k) >> 2) & 7) << 2);
}

__global__ void __launch_bounds__(256) k_scores(const float* __restrict__ x) {
    extern __shared__ float smem[];
    float* As = smem;              // [64][128]  As[k][i]
    float* Bs = smem + 64 * 128;   // [64][128]  Bs[k][j]

    int bj = blockIdx.x, bi = blockIdx.y, b = blockIdx.z;
    int i0 = bi * 128, j0 = bj * 128;
    const float* xb = x + (size_t)b * TT * DD;
    const float* eb = g_enc + (size_t)b * TT * DD;
    int tid = threadIdx.x;

    // fill: each thread 8 float4 per operand (coalesced global, swizzled STS)
    {
        int r  = tid >> 4;              // 0..15
        int k4 = (tid & 15) << 2;       // 0,4,...,60
        int sc;
#pragma unroll
        for (int it = 0; it < 8; it++) {
            int row = r + (it << 4);
            sc = swz(k4, row);
            float4 va = *(const float4*)(xb + (size_t)(i0 + row) * 64 + k4);
            As[(k4 + 0) * 128 + sc] = va.x;
            As[(k4 + 1) * 128 + sc] = va.y;
            As[(k4 + 2) * 128 + sc] = va.z;
            As[(k4 + 3) * 128 + sc] = va.w;
            float4 vb = *(const float4*)(eb + (size_t)(j0 + row) * 64 + k4);
            Bs[(k4 + 0) * 128 + sc] = vb.x;
            Bs[(k4 + 1) * 128 + sc] = vb.y;
            Bs[(k4 + 2) * 128 + sc] = vb.z;
            Bs[(k4 + 3) * 128 + sc] = vb.w;
        }
    }
    __syncthreads();

    int tx = tid & 15, ty = tid >> 4;
    float cr[8][8];
#pragma unroll
    for (int i = 0; i < 8; i++)
#pragma unroll
        for (int j = 0; j < 8; j++) cr[i][j] = 0.0f;

#pragma unroll 4
    for (int k = 0; k < 64; k++) {
        int f = ((k >> 2) & 7) << 2;
        float4 a0 = *(const float4*)&As[k * 128 + ((ty * 4) ^ f)];
        float4 a1 = *(const float4*)&As[k * 128 + (64 + ((ty * 4) ^ f))];
        float4 b0 = *(const float4*)&Bs[k * 128 + ((tx * 4) ^ f)];
        float4 b1 = *(const float4*)&Bs[k * 128 + (64 + ((tx * 4) ^ f))];
        float av[8] = {a0.x, a0.y, a0.z, a0.w, a1.x, a1.y, a1.z, a1.w};
        float bv[8] = {b0.x, b0.y, b0.z, b0.w, b1.x, b1.y, b1.z, b1.w};
#pragma unroll
        for (int ii = 0; ii < 8; ii++)
#pragma unroll
            for (int jj = 0; jj < 8; jj++)
                cr[ii][jj] = fmaf(av[ii], bv[jj], cr[ii][jj]);
    }

    float* sb = g_scores + (size_t)b * TT * TT;
#pragma unroll
    for (int ii = 0; ii < 8; ii++) {
        int il = (ii < 4) ? (ty * 4 + ii) : (64 + ty * 4 + ii - 4);
        size_t base = (size_t)(i0 + il) * TT + j0;
        float4 o0 = make_float4(cr[ii][0], cr[ii][1], cr[ii][2], cr[ii][3]);
        float4 o1 = make_float4(cr[ii][4], cr[ii][5], cr[ii][6], cr[ii][7]);
        *(float4*)(sb + base + tx * 4)      = o0;
        *(float4*)(sb + base + 64 + tx * 4) = o1;
    }
}

// ---------------------------------------------------------------------------
// K3: per-row softmax STATS only (no write-back of the 268MB buffer).
// One 256-thread block per (b,j) row: m = max_i s, invZ = 1/sum_i exp(s-m).
// ---------------------------------------------------------------------------
__global__ void __launch_bounds__(256) k_stats() {
    int j = blockIdx.x, b = blockIdx.y;
    const float* row = g_scores + (size_t)b * TT * TT + (size_t)j * TT;
    int tid = threadIdx.x;
    __shared__ float sred[8];
    __shared__ float sbc;

    float4 v[4];
    float m = -3.4e38f;
#pragma unroll
    for (int it = 0; it < 4; it++) {
        v[it] = *(const float4*)(row + ((it << 8) + tid) * 4);
        m = fmaxf(m, fmaxf(fmaxf(v[it].x, v[it].y), fmaxf(v[it].z, v[it].w)));
    }
#pragma unroll
    for (int o = 16; o > 0; o >>= 1) m = fmaxf(m, __shfl_xor_sync(0xffffffffu, m, o));
    if ((tid & 31) == 0) sred[tid >> 5] = m;
    __syncthreads();
    if (tid == 0) {
        float t = sred[0];
#pragma unroll
        for (int w = 1; w < 8; w++) t = fmaxf(t, sred[w]);
        sbc = t;
    }
    __syncthreads();
    m = sbc;
    __syncthreads();

    float s = 0.0f;
#pragma unroll
    for (int it = 0; it < 4; it++) {
        s += (__expf(v[it].x - m) + __expf(v[it].y - m)) +
             (__expf(v[it].z - m) + __expf(v[it].w - m));
    }
#pragma unroll
    for (int o = 16; o > 0; o >>= 1) s += __shfl_xor_sync(0xffffffffu, s, o);
    if ((tid & 31) == 0) sred[tid >> 5] = s;
    __syncthreads();
    if (tid == 0) {
        float t = 0.0f;
#pragma unroll
        for (int w = 0; w < 8; w++) t += sred[w];
        g_stats[(size_t)b * TT + j] = make_float2(m, 1.0f / t);
    }
}

// ---------------------------------------------------------------------------
// K4: out[b,i,d] = sum_j exp(S[b,j,i]-m_j)*invZ_j * x[b,j,d]   (A^T @ X)
// tile: 128 i x 64 d per block, loop j in chunks of 64. 8x4 per thread.
// Softmax weights materialized on the fly during the smem fill (MUFU-cheap).
// ---------------------------------------------------------------------------
__global__ void __launch_bounds__(256) k_out(const float* __restrict__ x,
                                             float* __restrict__ out) {
    __shared__ __align__(16) float As[64 * 128];  // As[jj][i_local] (weights)
    __shared__ __align__(16) float Xs[64 * 64];   // Xs[jj][d]

    int bi = blockIdx.x, b = blockIdx.y;
    int i0 = bi * 128;
    const float*  xb  = x + (size_t)b * TT * DD;
    const float*  att = g_scores + (size_t)b * TT * TT;
    const float2* st  = g_stats + (size_t)b * TT;
    float* outb = out + (size_t)b * TT * DD;

    int tid = threadIdx.x;
    int tx = tid & 15, ty = tid >> 4;

    float cr[8][4];
#pragma unroll
    for (int i = 0; i < 8; i++)
#pragma unroll
        for (int d = 0; d < 4; d++) cr[i][d] = 0.0f;

    // fill mappings
    int acol4 = (tid & 31) << 2;  // 0..124
    int ajj0  = tid >> 5;         // 0..7
    int xcol4 = (tid & 15) << 2;  // 0..60
    int xjj0  = tid >> 4;         // 0..15

    for (int j0 = 0; j0 < TT; j0 += 64) {
        __syncthreads();
#pragma unroll
        for (int it = 0; it < 8; it++) {
            int jj = ajj0 + (it << 3);
            float2 s = st[j0 + jj];                    // broadcast within warp
            float4 v = *(const float4*)(att + (size_t)(j0 + jj) * TT + i0 + acol4);
            v.x = __expf(v.x - s.x) * s.y;
            v.y = __expf(v.y - s.x) * s.y;
            v.z = __expf(v.z - s.x) * s.y;
            v.w = __expf(v.w - s.x) * s.y;
            *(float4*)&As[jj * 128 + acol4] = v;
        }
#pragma unroll
        for (int it = 0; it < 4; it++) {
            int jj = xjj0 + (it << 4);
            *(float4*)&Xs[jj * 64 + xcol4] =
                *(const float4*)(xb + (size_t)(j0 + jj) * 64 + xcol4);
        }
        __syncthreads();

#pragma unroll 8
        for (int jj = 0; jj < 64; jj++) {
            float4 xv = *(const float4*)&Xs[jj * 64 + tx * 4];
            float4 a0 = *(const float4*)&As[jj * 128 + ty * 4];
            float4 a1 = *(const float4*)&As[jj * 128 + 64 + ty * 4];
            float av[8] = {a0.x, a0.y, a0.z, a0.w, a1.x, a1.y, a1.z, a1.w};
            float xr[4] = {xv.x, xv.y, xv.z, xv.w};
#pragma unroll
            for (int ii = 0; ii < 8; ii++)
#pragma unroll
                for (int dd = 0; dd < 4; dd++)
                    cr[ii][dd] = fmaf(av[ii], xr[dd], cr[ii][dd]);
        }
    }

#pragma unroll
    for (int ii = 0; ii < 8; ii++) {
        int il = (ii < 4) ? (ty * 4 + ii) : (64 + ty * 4 + ii - 4);
        float4 o = make_float4(cr[ii][0], cr[ii][1], cr[ii][2], cr[ii][3]);
        *(float4*)(outb + (size_t)(i0 + il) * 64 + tx * 4) = o;
    }
}

// ---------------------------------------------------------------------------
extern "C" void kernel_launch(void* const* d_in, const int* in_sizes, int n_in,
                              void* d_out, int out_size) {
    const float* x  = (const float*)d_in[0];
    const float* W1 = (const float*)d_in[1];
    const float* b1 = (const float*)d_in[2];
    const float* W2 = (const float*)d_in[3];
    const float* b2 = (const float*)d_in[4];
    float* out = (float*)d_out;

    // K2 needs 64 KB dynamic shared
    static int smem_set = 0;
    if (!smem_set) {
        cudaFuncSetAttribute(k_scores, cudaFuncAttributeMaxDynamicSharedMemorySize,
                             64 * 128 * 2 * (int)sizeof(float));
        smem_set = 1;
    }

    k_encode<<<BB * TT, 64>>>(x, W1, b1, W2, b2);
    k_scores<<<dim3(TT / 128, TT / 128, BB), 256,
               64 * 128 * 2 * sizeof(float)>>>(x);
    k_stats<<<dim3(TT, BB), 256>>>();
    k_out<<<dim3(TT / 128, BB), 256>>>(x, out);
}

// round 5
// speedup vs baseline: 1.2308x; 1.2308x over previous
#include <cuda_runtime.h>
#include <math.h>

#define BB 4
#define TT 4096
#define DD 64
#define NCHUNK 4
#define JCHUNK (TT / NCHUNK)
#define NTILE 32              // TT/128 column tiles per row

// Scratch (device globals — allocation-free contract)
__device__ float  g_enc[(size_t)BB * TT * DD];              // 4 MB
__device__ float  g_scores[(size_t)BB * TT * TT];           // 268 MB
__device__ float2 g_pstats[(size_t)BB * TT * NTILE];        // 4 MB: per (row, tile128) {max, sumexp}
__device__ float2 g_stats[(size_t)BB * TT];                 // per row: {max, 1/Z}
__device__ float  g_partial[(size_t)NCHUNK * BB * TT * DD]; // 16 MB split-K partials

// ---------------------------------------------------------------------------
// K1: encoded = tanh(softmax(x@W1 + b1) @ W2 + b2)   one 64-thread block/token
// ---------------------------------------------------------------------------
__global__ void k_encode(const float* __restrict__ x,
                         const float* __restrict__ W1, const float* __restrict__ b1,
                         const float* __restrict__ W2, const float* __restrict__ b2) {
    int token = blockIdx.x;
    int t = threadIdx.x;                 // 0..63 = output feature
    __shared__ float xs[64];
    __shared__ float red[64];
    __shared__ float hs[64];

    xs[t] = x[(size_t)token * 64 + t];
    __syncthreads();

    float acc = b1[t];
#pragma unroll
    for (int d = 0; d < 64; d++) acc = fmaf(xs[d], W1[d * 64 + t], acc);

    red[t] = acc; __syncthreads();
#pragma unroll
    for (int s = 32; s > 0; s >>= 1) {
        if (t < s) red[t] = fmaxf(red[t], red[t + s]);
        __syncthreads();
    }
    float m = red[0];
    __syncthreads();
    float e = expf(acc - m);
    red[t] = e; __syncthreads();
#pragma unroll
    for (int s = 32; s > 0; s >>= 1) {
        if (t < s) red[t] = red[t] + red[t + s];
        __syncthreads();
    }
    float h = e / red[0];
    hs[t] = h;
    __syncthreads();

    float acc2 = b2[t];
#pragma unroll
    for (int d = 0; d < 64; d++) acc2 = fmaf(hs[d], W2[d * 64 + t], acc2);

    g_enc[(size_t)token * 64 + t] = tanhf(acc2);
}

// ---------------------------------------------------------------------------
// K2: scores[b,r,c] = <x[b,r,:], enc[b,c,:]>   128x128 tile, K=64 one-shot
// Also emits per-(row, 128-col-tile) partial softmax stats (max, sum-exp).
// ---------------------------------------------------------------------------
__device__ __forceinline__ int swz(int k, int col) {
    return col ^ ((((k) >> 2) & 7) << 2);
}

__global__ void __launch_bounds__(256) k_scores(const float* __restrict__ x) {
    extern __shared__ float smem[];
    float* As = smem;              // [64][128]  As[k][r]
    float* Bs = smem + 64 * 128;   // [64][128]  Bs[k][c]

    int bj = blockIdx.x, bi = blockIdx.y, b = blockIdx.z;
    int i0 = bi * 128, j0 = bj * 128;
    const float* xb = x + (size_t)b * TT * DD;
    const float* eb = g_enc + (size_t)b * TT * DD;
    int tid = threadIdx.x;

    {
        int r  = tid >> 4;              // 0..15
        int k4 = (tid & 15) << 2;       // 0,4,...,60
        int sc;
#pragma unroll
        for (int it = 0; it < 8; it++) {
            int row = r + (it << 4);
            sc = swz(k4, row);
            float4 va = *(const float4*)(xb + (size_t)(i0 + row) * 64 + k4);
            As[(k4 + 0) * 128 + sc] = va.x;
            As[(k4 + 1) * 128 + sc] = va.y;
            As[(k4 + 2) * 128 + sc] = va.z;
            As[(k4 + 3) * 128 + sc] = va.w;
            float4 vb = *(const float4*)(eb + (size_t)(j0 + row) * 64 + k4);
            Bs[(k4 + 0) * 128 + sc] = vb.x;
            Bs[(k4 + 1) * 128 + sc] = vb.y;
            Bs[(k4 + 2) * 128 + sc] = vb.z;
            Bs[(k4 + 3) * 128 + sc] = vb.w;
        }
    }
    __syncthreads();

    int tx = tid & 15, ty = tid >> 4;
    float cr[8][8];
#pragma unroll
    for (int i = 0; i < 8; i++)
#pragma unroll
        for (int j = 0; j < 8; j++) cr[i][j] = 0.0f;

#pragma unroll 4
    for (int k = 0; k < 64; k++) {
        int f = ((k >> 2) & 7) << 2;
        float4 a0 = *(const float4*)&As[k * 128 + ((ty * 4) ^ f)];
        float4 a1 = *(const float4*)&As[k * 128 + (64 + ((ty * 4) ^ f))];
        float4 b0 = *(const float4*)&Bs[k * 128 + ((tx * 4) ^ f)];
        float4 b1 = *(const float4*)&Bs[k * 128 + (64 + ((tx * 4) ^ f))];
        float av[8] = {a0.x, a0.y, a0.z, a0.w, a1.x, a1.y, a1.z, a1.w};
        float bv[8] = {b0.x, b0.y, b0.z, b0.w, b1.x, b1.y, b1.z, b1.w};
#pragma unroll
        for (int ii = 0; ii < 8; ii++)
#pragma unroll
            for (int jj = 0; jj < 8; jj++)
                cr[ii][jj] = fmaf(av[ii], bv[jj], cr[ii][jj]);
    }

    float* sb = g_scores + (size_t)b * TT * TT;
#pragma unroll
    for (int ii = 0; ii < 8; ii++) {
        int il = (ii < 4) ? (ty * 4 + ii) : (64 + ty * 4 + ii - 4);
        size_t base = (size_t)(i0 + il) * TT + j0;
        float4 o0 = make_float4(cr[ii][0], cr[ii][1], cr[ii][2], cr[ii][3]);
        float4 o1 = make_float4(cr[ii][4], cr[ii][5], cr[ii][6], cr[ii][7]);
        *(float4*)(sb + base + tx * 4)      = o0;
        *(float4*)(sb + base + 64 + tx * 4) = o1;
    }

    // Partial softmax stats for each of this thread's 8 rows, over the 128
    // columns of this tile. The 16 threads sharing a row (tx=0..15, fixed ty)
    // are contiguous lanes within a 16-lane shfl segment.
#pragma unroll
    for (int ii = 0; ii < 8; ii++) {
        float m = cr[ii][0];
#pragma unroll
        for (int jj = 1; jj < 8; jj++) m = fmaxf(m, cr[ii][jj]);
#pragma unroll
        for (int o = 1; o < 16; o <<= 1)
            m = fmaxf(m, __shfl_xor_sync(0xffffffffu, m, o, 16));
        float z = 0.0f;
#pragma unroll
        for (int jj = 0; jj < 8; jj++) z += __expf(cr[ii][jj] - m);
#pragma unroll
        for (int o = 1; o < 16; o <<= 1)
            z += __shfl_xor_sync(0xffffffffu, z, o, 16);
        if (tx == 0) {
            int il = (ii < 4) ? (ty * 4 + ii) : (64 + ty * 4 + ii - 4);
            g_pstats[((size_t)b * TT + i0 + il) * NTILE + bj] = make_float2(m, z);
        }
    }
}

// ---------------------------------------------------------------------------
// K3: reduce 32 per-tile partials per row -> {max, 1/Z}. One warp per row.
// ---------------------------------------------------------------------------
__global__ void __launch_bounds__(256) k_pstats_reduce() {
    int row = blockIdx.x * 8 + (threadIdx.x >> 5);   // global row 0..B*TT-1
    int lane = threadIdx.x & 31;
    float2 p = g_pstats[(size_t)row * NTILE + lane];
    float m = p.x;
#pragma unroll
    for (int o = 16; o > 0; o >>= 1) m = fmaxf(m, __shfl_xor_sync(0xffffffffu, m, o));
    float z = p.y * __expf(p.x - m);
#pragma unroll
    for (int o = 16; o > 0; o >>= 1) z += __shfl_xor_sync(0xffffffffu, z, o);
    if (lane == 0) g_stats[row] = make_float2(m, 1.0f / z);
}

// ---------------------------------------------------------------------------
// K4: split-K partials of out[b,i,d] = sum_j w_j(i) x[b,j,d]
// tile: 128 i x 64 d per block; each block covers one 1024-wide j chunk.
// Softmax weights materialized on the fly during the smem fill.
// ---------------------------------------------------------------------------
__global__ void __launch_bounds__(256) k_out(const float* __restrict__ x) {
    __shared__ __align__(16) float As[64 * 128];  // As[jj][i_local] (weights)
    __shared__ __align__(16) float Xs[64 * 64];   // Xs[jj][d]

    int bi = blockIdx.x, chunk = blockIdx.y, b = blockIdx.z;
    int i0 = bi * 128;
    const float*  xb  = x + (size_t)b * TT * DD;
    const float*  att = g_scores + (size_t)b * TT * TT;
    const float2* st  = g_stats + (size_t)b * TT;
    float* pout = g_partial + (size_t)chunk * BB * TT * DD + (size_t)b * TT * DD;

    int tid = threadIdx.x;
    int tx = tid & 15, ty = tid >> 4;

    float cr[8][4];
#pragma unroll
    for (int i = 0; i < 8; i++)
#pragma unroll
        for (int d = 0; d < 4; d++) cr[i][d] = 0.0f;

    int acol4 = (tid & 31) << 2;  // 0..124
    int ajj0  = tid >> 5;         // 0..7
    int xcol4 = (tid & 15) << 2;  // 0..60
    int xjj0  = tid >> 4;         // 0..15

    int jbeg = chunk * JCHUNK, jend = jbeg + JCHUNK;
    for (int j0 = jbeg; j0 < jend; j0 += 64) {
        __syncthreads();
#pragma unroll
        for (int it = 0; it < 8; it++) {
            int jj = ajj0 + (it << 3);
            float2 s = st[j0 + jj];
            float4 v = *(const float4*)(att + (size_t)(j0 + jj) * TT + i0 + acol4);
            v.x = __expf(v.x - s.x) * s.y;
            v.y = __expf(v.y - s.x) * s.y;
            v.z = __expf(v.z - s.x) * s.y;
            v.w = __expf(v.w - s.x) * s.y;
            *(float4*)&As[jj * 128 + acol4] = v;
        }
#pragma unroll
        for (int it = 0; it < 4; it++) {
            int jj = xjj0 + (it << 4);
            *(float4*)&Xs[jj * 64 + xcol4] =
                *(const float4*)(xb + (size_t)(j0 + jj) * 64 + xcol4);
        }
        __syncthreads();

#pragma unroll 8
        for (int jj = 0; jj < 64; jj++) {
            float4 xv = *(const float4*)&Xs[jj * 64 + tx * 4];
            float4 a0 = *(const float4*)&As[jj * 128 + ty * 4];
            float4 a1 = *(const float4*)&As[jj * 128 + 64 + ty * 4];
            float av[8] = {a0.x, a0.y, a0.z, a0.w, a1.x, a1.y, a1.z, a1.w};
            float xr[4] = {xv.x, xv.y, xv.z, xv.w};
#pragma unroll
            for (int ii = 0; ii < 8; ii++)
#pragma unroll
                for (int dd = 0; dd < 4; dd++)
                    cr[ii][dd] = fmaf(av[ii], xr[dd], cr[ii][dd]);
        }
    }

#pragma unroll
    for (int ii = 0; ii < 8; ii++) {
        int il = (ii < 4) ? (ty * 4 + ii) : (64 + ty * 4 + ii - 4);
        float4 o = make_float4(cr[ii][0], cr[ii][1], cr[ii][2], cr[ii][3]);
        *(float4*)(pout + (size_t)(i0 + il) * 64 + tx * 4) = o;
    }
}

// ---------------------------------------------------------------------------
// K5: out = sum over NCHUNK partials (deterministic, no atomics).
// ---------------------------------------------------------------------------
__global__ void __launch_bounds__(256) k_final(float* __restrict__ out) {
    size_t idx4 = (size_t)blockIdx.x * 256 + threadIdx.x;   // float4 index
    const size_t N4 = (size_t)BB * TT * DD / 4;
    if (idx4 >= N4) return;
    const float4* p = (const float4*)g_partial;
    float4 a = p[idx4];
    float4 b = p[N4 + idx4];
    float4 c = p[2 * N4 + idx4];
    float4 d = p[3 * N4 + idx4];
    float4 o;
    o.x = (a.x + b.x) + (c.x + d.x);
    o.y = (a.y + b.y) + (c.y + d.y);
    o.z = (a.z + b.z) + (c.z + d.z);
    o.w = (a.w + b.w) + (c.w + d.w);
    ((float4*)out)[idx4] = o;
}

// ---------------------------------------------------------------------------
extern "C" void kernel_launch(void* const* d_in, const int* in_sizes, int n_in,
                              void* d_out, int out_size) {
    const float* x  = (const float*)d_in[0];
    const float* W1 = (const float*)d_in[1];
    const float* b1 = (const float*)d_in[2];
    const float* W2 = (const float*)d_in[3];
    const float* b2 = (const float*)d_in[4];
    float* out = (float*)d_out;

    static int smem_set = 0;
    if (!smem_set) {
        cudaFuncSetAttribute(k_scores, cudaFuncAttributeMaxDynamicSharedMemorySize,
                             64 * 128 * 2 * (int)sizeof(float));
        smem_set = 1;
    }

    k_encode<<<BB * TT, 64>>>(x, W1, b1, W2, b2);
    k_scores<<<dim3(TT / 128, TT / 128, BB), 256,
               64 * 128 * 2 * sizeof(float)>>>(x);
    k_pstats_reduce<<<BB * TT / 8, 256>>>();
    k_out<<<dim3(TT / 128, NCHUNK, BB), 256>>>(x);
    k_final<<<(BB * TT * DD / 4 + 255) / 256, 256>>>(out);
}

// round 12
// speedup vs baseline: 1.3560x; 1.1018x over previous
#include <cuda_runtime.h>
#include <math.h>

#define BB 4
#define TT 4096
#define DD 64
#define NCHUNK 4
#define JCHUNK (TT / NCHUNK)
#define NTILE 32              // TT/128 column tiles per row

// Scratch (device globals — allocation-free contract)
__device__ float  g_enc[(size_t)BB * TT * DD];              // 4 MB
__device__ float  g_scores[(size_t)BB * TT * TT];           // 268 MB
__device__ float2 g_pstats[(size_t)BB * TT * NTILE];        // 4 MB
__device__ float2 g_stats[(size_t)BB * TT];                 // per row: {max, 1/Z}
__device__ float  g_partial[(size_t)NCHUNK * BB * TT * DD]; // 16 MB split-K partials

// ---- packed f32x2 helpers (sm_10x FFMA2 path; exact IEEE fp32 per lane) ----
__device__ __forceinline__ unsigned long long f2_dup(float v) {
    unsigned long long r;
    asm("mov.b64 %0, {%1, %1};" : "=l"(r) : "f"(v));
    return r;
}
__device__ __forceinline__ unsigned long long f2_fma(unsigned long long a,
                                                     unsigned long long b,
                                                     unsigned long long c) {
    unsigned long long d;
    asm("fma.rn.f32x2 %0, %1, %2, %3;" : "=l"(d) : "l"(a), "l"(b), "l"(c));
    return d;
}
__device__ __forceinline__ float2 f2_unpack(unsigned long long v) {
    float lo, hi;
    asm("mov.b64 {%0, %1}, %2;" : "=f"(lo), "=f"(hi) : "l"(v));
    return make_float2(lo, hi);
}

// ---------------------------------------------------------------------------
// K1: encoded = tanh(softmax(x@W1 + b1) @ W2 + b2)   one 64-thread block/token
// ---------------------------------------------------------------------------
__global__ void k_encode(const float* __restrict__ x,
                         const float* __restrict__ W1, const float* __restrict__ b1,
                         const float* __restrict__ W2, const float* __restrict__ b2) {
    int token = blockIdx.x;
    int t = threadIdx.x;
    __shared__ float xs[64];
    __shared__ float red[64];
    __shared__ float hs[64];

    xs[t] = x[(size_t)token * 64 + t];
    __syncthreads();

    float acc = b1[t];
#pragma unroll
    for (int d = 0; d < 64; d++) acc = fmaf(xs[d], W1[d * 64 + t], acc);

    red[t] = acc; __syncthreads();
#pragma unroll
    for (int s = 32; s > 0; s >>= 1) {
        if (t < s) red[t] = fmaxf(red[t], red[t + s]);
        __syncthreads();
    }
    float m = red[0];
    __syncthreads();
    float e = expf(acc - m);
    red[t] = e; __syncthreads();
#pragma unroll
    for (int s = 32; s > 0; s >>= 1) {
        if (t < s) red[t] = red[t] + red[t + s];
        __syncthreads();
    }
    float h = e / red[0];
    hs[t] = h;
    __syncthreads();

    float acc2 = b2[t];
#pragma unroll
    for (int d = 0; d < 64; d++) acc2 = fmaf(hs[d], W2[d * 64 + t], acc2);

    g_enc[(size_t)token * 64 + t] = tanhf(acc2);
}

// ---------------------------------------------------------------------------
// K2: scores tile 128x128, K=64 one-shot, FFMA2 mainloop (i-pairs packed).
// Also emits per-(row, tile128) partial softmax stats.
// ---------------------------------------------------------------------------
__device__ __forceinline__ int swz(int k, int col) {
    return col ^ ((((k) >> 2) & 7) << 2);
}

__global__ void __launch_bounds__(256) k_scores(const float* __restrict__ x) {
    extern __shared__ float smem[];
    float* As = smem;              // [64][128]  As[k][r]
    float* Bs = smem + 64 * 128;   // [64][128]  Bs[k][c]

    int bj = blockIdx.x, bi = blockIdx.y, b = blockIdx.z;
    int i0 = bi * 128, j0 = bj * 128;
    const float* xb = x + (size_t)b * TT * DD;
    const float* eb = g_enc + (size_t)b * TT * DD;
    int tid = threadIdx.x;

    {
        int r  = tid >> 4;
        int k4 = (tid & 15) << 2;
        int sc;
#pragma unroll
        for (int it = 0; it < 8; it++) {
            int row = r + (it << 4);
            sc = swz(k4, row);
            float4 va = *(const float4*)(xb + (size_t)(i0 + row) * 64 + k4);
            As[(k4 + 0) * 128 + sc] = va.x;
            As[(k4 + 1) * 128 + sc] = va.y;
            As[(k4 + 2) * 128 + sc] = va.z;
            As[(k4 + 3) * 128 + sc] = va.w;
            float4 vb = *(const float4*)(eb + (size_t)(j0 + row) * 64 + k4);
            Bs[(k4 + 0) * 128 + sc] = vb.x;
            Bs[(k4 + 1) * 128 + sc] = vb.y;
            Bs[(k4 + 2) * 128 + sc] = vb.z;
            Bs[(k4 + 3) * 128 + sc] = vb.w;
        }
    }
    __syncthreads();

    int tx = tid & 15, ty = tid >> 4;

    // cr2[ip][j]: packed pair of i-rows. ip0->(ty*4+0,+1) ip1->(+2,+3)
    //             ip2->(64+ty*4+0,+1) ip3->(64+ty*4+2,+3)
    unsigned long long cr2[4][8];
#pragma unroll
    for (int i = 0; i < 4; i++)
#pragma unroll
        for (int j = 0; j < 8; j++) cr2[i][j] = 0ull;

#pragma unroll 4
    for (int k = 0; k < 64; k++) {
        int f = ((k >> 2) & 7) << 2;
        // A pairs: 16B loads land as pre-packed 64-bit register pairs
        ulonglong2 ap0 = *(const ulonglong2*)&As[k * 128 + ((ty * 4) ^ f)];
        ulonglong2 ap1 = *(const ulonglong2*)&As[k * 128 + (64 + ((ty * 4) ^ f))];
        unsigned long long ap[4] = {ap0.x, ap0.y, ap1.x, ap1.y};
        float4 b0 = *(const float4*)&Bs[k * 128 + ((tx * 4) ^ f)];
        float4 b1 = *(const float4*)&Bs[k * 128 + (64 + ((tx * 4) ^ f))];
        unsigned long long bd[8] = {f2_dup(b0.x), f2_dup(b0.y), f2_dup(b0.z), f2_dup(b0.w),
                                    f2_dup(b1.x), f2_dup(b1.y), f2_dup(b1.z), f2_dup(b1.w)};
#pragma unroll
        for (int ip = 0; ip < 4; ip++)
#pragma unroll
            for (int jj = 0; jj < 8; jj++)
                cr2[ip][jj] = f2_fma(ap[ip], bd[jj], cr2[ip][jj]);
    }

    float* sb = g_scores + (size_t)b * TT * TT;
#pragma unroll
    for (int ip = 0; ip < 4; ip++) {
        int rlo = (ip < 2) ? (ty * 4 + ip * 2) : (64 + ty * 4 + (ip - 2) * 2);
        float vlo[8], vhi[8];
#pragma unroll
        for (int jj = 0; jj < 8; jj++) {
            float2 u = f2_unpack(cr2[ip][jj]);
            vlo[jj] = u.x; vhi[jj] = u.y;
        }
        size_t blo = (size_t)(i0 + rlo) * TT + j0;
        size_t bhi = (size_t)(i0 + rlo + 1) * TT + j0;
        *(float4*)(sb + blo + tx * 4)      = make_float4(vlo[0], vlo[1], vlo[2], vlo[3]);
        *(float4*)(sb + blo + 64 + tx * 4) = make_float4(vlo[4], vlo[5], vlo[6], vlo[7]);
        *(float4*)(sb + bhi + tx * 4)      = make_float4(vhi[0], vhi[1], vhi[2], vhi[3]);
        *(float4*)(sb + bhi + 64 + tx * 4) = make_float4(vhi[4], vhi[5], vhi[6], vhi[7]);

        // per-row partial stats over this tile's 128 columns
#pragma unroll
        for (int half = 0; half < 2; half++) {
            const float* vv = half ? vhi : vlo;
            float m = vv[0];
#pragma unroll
            for (int jj = 1; jj < 8; jj++) m = fmaxf(m, vv[jj]);
#pragma unroll
            for (int o = 1; o < 16; o <<= 1)
                m = fmaxf(m, __shfl_xor_sync(0xffffffffu, m, o, 16));
            float z = 0.0f;
#pragma unroll
            for (int jj = 0; jj < 8; jj++) z += __expf(vv[jj] - m);
#pragma unroll
            for (int o = 1; o < 16; o <<= 1)
                z += __shfl_xor_sync(0xffffffffu, z, o, 16);
            if (tx == 0)
                g_pstats[((size_t)b * TT + i0 + rlo + half) * NTILE + bj] =
                    make_float2(m, z);
        }
    }
}

// ---------------------------------------------------------------------------
// K3: reduce 32 per-tile partials per row -> {max, 1/Z}. One warp per row.
// ---------------------------------------------------------------------------
__global__ void __launch_bounds__(256) k_pstats_reduce() {
    int row = blockIdx.x * 8 + (threadIdx.x >> 5);
    int lane = threadIdx.x & 31;
    float2 p = g_pstats[(size_t)row * NTILE + lane];
    float m = p.x;
#pragma unroll
    for (int o = 16; o > 0; o >>= 1) m = fmaxf(m, __shfl_xor_sync(0xffffffffu, m, o));
    float z = p.y * __expf(p.x - m);
#pragma unroll
    for (int o = 16; o > 0; o >>= 1) z += __shfl_xor_sync(0xffffffffu, z, o);
    if (lane == 0) g_stats[row] = make_float2(m, 1.0f / z);
}

// ---------------------------------------------------------------------------
// K4: split-K partials of out[b,i,d] = sum_j w_j(i) x[b,j,d], FFMA2 mainloop.
// ---------------------------------------------------------------------------
__global__ void __launch_bounds__(256) k_out(const float* __restrict__ x) {
    __shared__ __align__(16) float As[64 * 128];  // As[jj][i_local] (weights)
    __shared__ __align__(16) float Xs[64 * 64];   // Xs[jj][d]

    int bi = blockIdx.x, chunk = blockIdx.y, b = blockIdx.z;
    int i0 = bi * 128;
    const float*  xb  = x + (size_t)b * TT * DD;
    const float*  att = g_scores + (size_t)b * TT * TT;
    const float2* st  = g_stats + (size_t)b * TT;
    float* pout = g_partial + (size_t)chunk * BB * TT * DD + (size_t)b * TT * DD;

    int tid = threadIdx.x;
    int tx = tid & 15, ty = tid >> 4;

    // cr2[ip][dd]: packed pair of i-rows (same pair map as k_scores).
    unsigned long long cr2[4][4];
#pragma unroll
    for (int i = 0; i < 4; i++)
#pragma unroll
        for (int d = 0; d < 4; d++) cr2[i][d] = 0ull;

    int acol4 = (tid & 31) << 2;
    int ajj0  = tid >> 5;
    int xcol4 = (tid & 15) << 2;
    int xjj0  = tid >> 4;

    int jbeg = chunk * JCHUNK, jend = jbeg + JCHUNK;
    for (int j0 = jbeg; j0 < jend; j0 += 64) {
        __syncthreads();
#pragma unroll
        for (int it = 0; it < 8; it++) {
            int jj = ajj0 + (it << 3);
            float2 s = st[j0 + jj];
            float4 v = *(const float4*)(att + (size_t)(j0 + jj) * TT + i0 + acol4);
            v.x = __expf(v.x - s.x) * s.y;
            v.y = __expf(v.y - s.x) * s.y;
            v.z = __expf(v.z - s.x) * s.y;
            v.w = __expf(v.w - s.x) * s.y;
            *(float4*)&As[jj * 128 + acol4] = v;
        }
#pragma unroll
        for (int it = 0; it < 4; it++) {
            int jj = xjj0 + (it << 4);
            *(float4*)&Xs[jj * 64 + xcol4] =
                *(const float4*)(xb + (size_t)(j0 + jj) * 64 + xcol4);
        }
        __syncthreads();

#pragma unroll 8
        for (int jj = 0; jj < 64; jj++) {
            float4 xv = *(const float4*)&Xs[jj * 64 + tx * 4];
            ulonglong2 ap0 = *(const ulonglong2*)&As[jj * 128 + ty * 4];
            ulonglong2 ap1 = *(const ulonglong2*)&As[jj * 128 + 64 + ty * 4];
            unsigned long long ap[4] = {ap0.x, ap0.y, ap1.x, ap1.y};
            unsigned long long xd[4] = {f2_dup(xv.x), f2_dup(xv.y),
                                        f2_dup(xv.z), f2_dup(xv.w)};
#pragma unroll
            for (int ip = 0; ip < 4; ip++)
#pragma unroll
                for (int dd = 0; dd < 4; dd++)
                    cr2[ip][dd] = f2_fma(ap[ip], xd[dd], cr2[ip][dd]);
        }
    }

#pragma unroll
    for (int ip = 0; ip < 4; ip++) {
        int rlo = (ip < 2) ? (ty * 4 + ip * 2) : (64 + ty * 4 + (ip - 2) * 2);
        float2 u0 = f2_unpack(cr2[ip][0]);
        float2 u1 = f2_unpack(cr2[ip][1]);
        float2 u2 = f2_unpack(cr2[ip][2]);
        float2 u3 = f2_unpack(cr2[ip][3]);
        *(float4*)(pout + (size_t)(i0 + rlo) * 64 + tx * 4) =
            make_float4(u0.x, u1.x, u2.x, u3.x);
        *(float4*)(pout + (size_t)(i0 + rlo + 1) * 64 + tx * 4) =
            make_float4(u0.y, u1.y, u2.y, u3.y);
    }
}

// ---------------------------------------------------------------------------
// K5: out = sum over NCHUNK partials (deterministic, no atomics).
// ---------------------------------------------------------------------------
__global__ void __launch_bounds__(256) k_final(float* __restrict__ out) {
    size_t idx4 = (size_t)blockIdx.x * 256 + threadIdx.x;
    const size_t N4 = (size_t)BB * TT * DD / 4;
    if (idx4 >= N4) return;
    const float4* p = (const float4*)g_partial;
    float4 a = p[idx4];
    float4 b = p[N4 + idx4];
    float4 c = p[2 * N4 + idx4];
    float4 d = p[3 * N4 + idx4];
    float4 o;
    o.x = (a.x + b.x) + (c.x + d.x);
    o.y = (a.y + b.y) + (c.y + d.y);
    o.z = (a.z + b.z) + (c.z + d.z);
    o.w = (a.w + b.w) + (c.w + d.w);
    ((float4*)out)[idx4] = o;
}

// ---------------------------------------------------------------------------
extern "C" void kernel_launch(void* const* d_in, const int* in_sizes, int n_in,
                              void* d_out, int out_size) {
    const float* x  = (const float*)d_in[0];
    const float* W1 = (const float*)d_in[1];
    const float* b1 = (const float*)d_in[2];
    const float* W2 = (const float*)d_in[3];
    const float* b2 = (const float*)d_in[4];
    float* out = (float*)d_out;

    static int smem_set = 0;
    if (!smem_set) {
        cudaFuncSetAttribute(k_scores, cudaFuncAttributeMaxDynamicSharedMemorySize,
                             64 * 128 * 2 * (int)sizeof(float));
        smem_set = 1;
    }

    k_encode<<<BB * TT, 64>>>(x, W1, b1, W2, b2);
    k_scores<<<dim3(TT / 128, TT / 128, BB), 256,
               64 * 128 * 2 * sizeof(float)>>>(x);
    k_pstats_reduce<<<BB * TT / 8, 256>>>();
    k_out<<<dim3(TT / 128, NCHUNK, BB), 256>>>(x);
    k_final<<<(BB * TT * DD / 4 + 255) / 256, 256>>>(out);
}

// round 13
// speedup vs baseline: 1.6224x; 1.1965x over previous
#include <cuda_runtime.h>
#include <cuda_bf16.h>
#include <math.h>
#include <stdint.h>

#define BB 4
#define TT 4096
#define DD 64
#define NCHUNK 4
#define JCHUNK (TT / NCHUNK)
#define NTILE 32              // TT/128 column tiles per row

// Scratch (device globals — allocation-free contract)
__device__ float  g_enc[(size_t)BB * TT * DD];              // 4 MB
__device__ float  g_scores[(size_t)BB * TT * TT];           // 268 MB
__device__ float2 g_pstats[(size_t)BB * TT * NTILE];        // 4 MB
__device__ float2 g_stats[(size_t)BB * TT];                 // per row: {max, 1/Z}
__device__ float  g_partial[(size_t)NCHUNK * BB * TT * DD]; // 16 MB split-K partials

// ---- packed f32x2 helpers (sm_10x FFMA2 path; exact IEEE fp32 per lane) ----
__device__ __forceinline__ unsigned long long f2_dup(float v) {
    unsigned long long r;
    asm("mov.b64 %0, {%1, %1};" : "=l"(r) : "f"(v));
    return r;
}
__device__ __forceinline__ unsigned long long f2_fma(unsigned long long a,
                                                     unsigned long long b,
                                                     unsigned long long c) {
    unsigned long long d;
    asm("fma.rn.f32x2 %0, %1, %2, %3;" : "=l"(d) : "l"(a), "l"(b), "l"(c));
    return d;
}
__device__ __forceinline__ float2 f2_unpack(unsigned long long v) {
    float lo, hi;
    asm("mov.b64 {%0, %1}, %2;" : "=f"(lo), "=f"(hi) : "l"(v));
    return make_float2(lo, hi);
}

// ---- bf16 split helpers ----
__device__ __forceinline__ void bf16_split2(float v0, float v1,
                                            uint32_t& hi, uint32_t& lo) {
    __nv_bfloat16 h0 = __float2bfloat16(v0);
    __nv_bfloat16 h1 = __float2bfloat16(v1);
    float r0 = v0 - __bfloat162float(h0);
    float r1 = v1 - __bfloat162float(h1);
    __nv_bfloat162 hp; hp.x = h0; hp.y = h1;
    __nv_bfloat162 lp; lp.x = __float2bfloat16(r0); lp.y = __float2bfloat16(r1);
    hi = *(uint32_t*)&hp;
    lo = *(uint32_t*)&lp;
}

// mma.sync m16n8k16 row.col bf16 -> fp32 accumulate in place
__device__ __forceinline__ void mma16816(float* c, const uint32_t* a, const uint32_t* b) {
    asm volatile(
        "mma.sync.aligned.m16n8k16.row.col.f32.bf16.bf16.f32 "
        "{%0,%1,%2,%3}, {%4,%5,%6,%7}, {%8,%9}, {%0,%1,%2,%3};"
        : "+f"(c[0]), "+f"(c[1]), "+f"(c[2]), "+f"(c[3])
        : "r"(a[0]), "r"(a[1]), "r"(a[2]), "r"(a[3]), "r"(b[0]), "r"(b[1]));
}

// ---------------------------------------------------------------------------
// K1: encoded = tanh(softmax(x@W1 + b1) @ W2 + b2)   one 64-thread block/token
// ---------------------------------------------------------------------------
__global__ void k_encode(const float* __restrict__ x,
                         const float* __restrict__ W1, const float* __restrict__ b1,
                         const float* __restrict__ W2, const float* __restrict__ b2) {
    int token = blockIdx.x;
    int t = threadIdx.x;
    __shared__ float xs[64];
    __shared__ float red[64];
    __shared__ float hs[64];

    xs[t] = x[(size_t)token * 64 + t];
    __syncthreads();

    float acc = b1[t];
#pragma unroll
    for (int d = 0; d < 64; d++) acc = fmaf(xs[d], W1[d * 64 + t], acc);

    red[t] = acc; __syncthreads();
#pragma unroll
    for (int s = 32; s > 0; s >>= 1) {
        if (t < s) red[t] = fmaxf(red[t], red[t + s]);
        __syncthreads();
    }
    float m = red[0];
    __syncthreads();
    float e = expf(acc - m);
    red[t] = e; __syncthreads();
#pragma unroll
    for (int s = 32; s > 0; s >>= 1) {
        if (t < s) red[t] = red[t] + red[t + s];
        __syncthreads();
    }
    float h = e / red[0];
    hs[t] = h;
    __syncthreads();

    float acc2 = b2[t];
#pragma unroll
    for (int d = 0; d < 64; d++) acc2 = fmaf(hs[d], W2[d * 64 + t], acc2);

    g_enc[(size_t)token * 64 + t] = tanhf(acc2);
}

// ---------------------------------------------------------------------------
// K2: scores tile 128x128, K=64 one-shot, FFMA2 mainloop (unchanged from R12).
// ---------------------------------------------------------------------------
__device__ __forceinline__ int swz(int k, int col) {
    return col ^ ((((k) >> 2) & 7) << 2);
}

__global__ void __launch_bounds__(256) k_scores(const float* __restrict__ x) {
    extern __shared__ float smem[];
    float* As = smem;              // [64][128]  As[k][r]
    float* Bs = smem + 64 * 128;   // [64][128]  Bs[k][c]

    int bj = blockIdx.x, bi = blockIdx.y, b = blockIdx.z;
    int i0 = bi * 128, j0 = bj * 128;
    const float* xb = x + (size_t)b * TT * DD;
    const float* eb = g_enc + (size_t)b * TT * DD;
    int tid = threadIdx.x;

    {
        int r  = tid >> 4;
        int k4 = (tid & 15) << 2;
        int sc;
#pragma unroll
        for (int it = 0; it < 8; it++) {
            int row = r + (it << 4);
            sc = swz(k4, row);
            float4 va = *(const float4*)(xb + (size_t)(i0 + row) * 64 + k4);
            As[(k4 + 0) * 128 + sc] = va.x;
            As[(k4 + 1) * 128 + sc] = va.y;
            As[(k4 + 2) * 128 + sc] = va.z;
            As[(k4 + 3) * 128 + sc] = va.w;
            float4 vb = *(const float4*)(eb + (size_t)(j0 + row) * 64 + k4);
            Bs[(k4 + 0) * 128 + sc] = vb.x;
            Bs[(k4 + 1) * 128 + sc] = vb.y;
            Bs[(k4 + 2) * 128 + sc] = vb.z;
            Bs[(k4 + 3) * 128 + sc] = vb.w;
        }
    }
    __syncthreads();

    int tx = tid & 15, ty = tid >> 4;

    unsigned long long cr2[4][8];
#pragma unroll
    for (int i = 0; i < 4; i++)
#pragma unroll
        for (int j = 0; j < 8; j++) cr2[i][j] = 0ull;

#pragma unroll 4
    for (int k = 0; k < 64; k++) {
        int f = ((k >> 2) & 7) << 2;
        ulonglong2 ap0 = *(const ulonglong2*)&As[k * 128 + ((ty * 4) ^ f)];
        ulonglong2 ap1 = *(const ulonglong2*)&As[k * 128 + (64 + ((ty * 4) ^ f))];
        unsigned long long ap[4] = {ap0.x, ap0.y, ap1.x, ap1.y};
        float4 b0 = *(const float4*)&Bs[k * 128 + ((tx * 4) ^ f)];
        float4 b1 = *(const float4*)&Bs[k * 128 + (64 + ((tx * 4) ^ f))];
        unsigned long long bd[8] = {f2_dup(b0.x), f2_dup(b0.y), f2_dup(b0.z), f2_dup(b0.w),
                                    f2_dup(b1.x), f2_dup(b1.y), f2_dup(b1.z), f2_dup(b1.w)};
#pragma unroll
        for (int ip = 0; ip < 4; ip++)
#pragma unroll
            for (int jj = 0; jj < 8; jj++)
                cr2[ip][jj] = f2_fma(ap[ip], bd[jj], cr2[ip][jj]);
    }

    float* sb = g_scores + (size_t)b * TT * TT;
#pragma unroll
    for (int ip = 0; ip < 4; ip++) {
        int rlo = (ip < 2) ? (ty * 4 + ip * 2) : (64 + ty * 4 + (ip - 2) * 2);
        float vlo[8], vhi[8];
#pragma unroll
        for (int jj = 0; jj < 8; jj++) {
            float2 u = f2_unpack(cr2[ip][jj]);
            vlo[jj] = u.x; vhi[jj] = u.y;
        }
        size_t blo = (size_t)(i0 + rlo) * TT + j0;
        size_t bhi = (size_t)(i0 + rlo + 1) * TT + j0;
        *(float4*)(sb + blo + tx * 4)      = make_float4(vlo[0], vlo[1], vlo[2], vlo[3]);
        *(float4*)(sb + blo + 64 + tx * 4) = make_float4(vlo[4], vlo[5], vlo[6], vlo[7]);
        *(float4*)(sb + bhi + tx * 4)      = make_float4(vhi[0], vhi[1], vhi[2], vhi[3]);
        *(float4*)(sb + bhi + 64 + tx * 4) = make_float4(vhi[4], vhi[5], vhi[6], vhi[7]);

#pragma unroll
        for (int half = 0; half < 2; half++) {
            const float* vv = half ? vhi : vlo;
            float m = vv[0];
#pragma unroll
            for (int jj = 1; jj < 8; jj++) m = fmaxf(m, vv[jj]);
#pragma unroll
            for (int o = 1; o < 16; o <<= 1)
                m = fmaxf(m, __shfl_xor_sync(0xffffffffu, m, o, 16));
            float z = 0.0f;
#pragma unroll
            for (int jj = 0; jj < 8; jj++) z += __expf(vv[jj] - m);
#pragma unroll
            for (int o = 1; o < 16; o <<= 1)
                z += __shfl_xor_sync(0xffffffffu, z, o, 16);
            if (tx == 0)
                g_pstats[((size_t)b * TT + i0 + rlo + half) * NTILE + bj] =
                    make_float2(m, z);
        }
    }
}

// ---------------------------------------------------------------------------
// K3: reduce 32 per-tile partials per row -> {max, 1/Z}. One warp per row.
// ---------------------------------------------------------------------------
__global__ void __launch_bounds__(256) k_pstats_reduce() {
    int row = blockIdx.x * 8 + (threadIdx.x >> 5);
    int lane = threadIdx.x & 31;
    float2 p = g_pstats[(size_t)row * NTILE + lane];
    float m = p.x;
#pragma unroll
    for (int o = 16; o > 0; o >>= 1) m = fmaxf(m, __shfl_xor_sync(0xffffffffu, m, o));
    float z = p.y * __expf(p.x - m);
#pragma unroll
    for (int o = 16; o > 0; o >>= 1) z += __shfl_xor_sync(0xffffffffu, z, o);
    if (lane == 0) g_stats[row] = make_float2(m, 1.0f / z);
}

// ---------------------------------------------------------------------------
// K4: split-K partials of out[b,i,d] = sum_j w_j(i) x[b,j,d]
// NEW: tensor-core mainloop (mma.sync m16n8k16 bf16, hi/lo split, fp32 acc).
// CTA 256 thr = 8 warps; tile 128(i) x 64(d); 64-j smem blocks.
// Smem word-layouts (stride 36 u32 per row) make all fragment LDS conflict-free.
// ---------------------------------------------------------------------------
#define KOUT_SMEM_BYTES ((2 * 128 * 36 + 2 * 64 * 36) * 4)   // 55296

__global__ void __launch_bounds__(256) k_out(const float* __restrict__ x) {
    extern __shared__ __align__(16) uint32_t sw[];
    uint32_t* Whw = sw;                       // W hi  [128 i][36 w]
    uint32_t* Wlw = Whw + 128 * 36;           // W lo
    uint32_t* Xhw = Wlw + 128 * 36;           // X hi  [64 d][36 w]
    uint32_t* Xlw = Xhw + 64 * 36;            // X lo

    int bi = blockIdx.x, chunk = blockIdx.y, b = blockIdx.z;
    int i0 = bi * 128;
    const float*  xb  = x + (size_t)b * TT * DD;
    const float*  att = g_scores + (size_t)b * TT * TT;
    const float2* st  = g_stats + (size_t)b * TT;
    float* pout = g_partial + ((size_t)chunk * BB + b) * TT * DD;

    int tid  = threadIdx.x;
    int lane = tid & 31;
    int wid  = tid >> 5;
    int warpM = wid & 3;          // 4 warps x 32 rows = 128 i
    int warpN = wid >> 2;         // 2 warps x 32 cols = 64 d
    int r = lane >> 2, q = lane & 3;

    int jp = tid >> 3;            // 0..31 -> j pair (2 j's per u32)
    int l8 = tid & 7;

    float c[2][4][4];
#pragma unroll
    for (int mt = 0; mt < 2; mt++)
#pragma unroll
        for (int nt = 0; nt < 4; nt++)
#pragma unroll
            for (int e = 0; e < 4; e++) c[mt][nt][e] = 0.0f;

    int jbeg = chunk * JCHUNK, jend = jbeg + JCHUNK;
    for (int j0 = jbeg; j0 < jend; j0 += 64) {
        __syncthreads();
        // --- W fill: w = exp(att[j][i]-m_j)*invZ_j, split hi/lo, store [i][j] ---
        {
            int ja = j0 + 2 * jp;
            float2 s0 = st[ja], s1 = st[ja + 1];
            const float* a0 = att + (size_t)ja * TT + i0;
            const float* a1 = a0 + TT;
#pragma unroll
            for (int t = 0; t < 16; t++) {
                int i = l8 + 8 * t;
                float w0 = __expf(a0[i] - s0.x) * s0.y;
                float w1 = __expf(a1[i] - s1.x) * s1.y;
                uint32_t hi, lo;
                bf16_split2(w0, w1, hi, lo);
                Whw[i * 36 + jp] = hi;
                Wlw[i * 36 + jp] = lo;
            }
        }
        // --- X fill: split hi/lo, store transposed [d][j] ---
        {
            const float* x0 = xb + (size_t)(j0 + 2 * jp) * 64;
            const float* x1 = x0 + 64;
#pragma unroll
            for (int t = 0; t < 8; t++) {
                int d = l8 + 8 * t;
                uint32_t hi, lo;
                bf16_split2(x0[d], x1[d], hi, lo);
                Xhw[d * 36 + jp] = hi;
                Xlw[d * 36 + jp] = lo;
            }
        }
        __syncthreads();

        // --- MMA mainloop: 4 k-steps of 16 over this 64-j block ---
#pragma unroll
        for (int kk = 0; kk < 4; kk++) {
            uint32_t ah[2][4], al[2][4];
#pragma unroll
            for (int mt = 0; mt < 2; mt++) {
                int w0 = (warpM * 32 + mt * 16 + r) * 36 + kk * 8 + q;
                ah[mt][0] = Whw[w0];       ah[mt][1] = Whw[w0 + 288];
                ah[mt][2] = Whw[w0 + 4];   ah[mt][3] = Whw[w0 + 292];
                al[mt][0] = Wlw[w0];       al[mt][1] = Wlw[w0 + 288];
                al[mt][2] = Wlw[w0 + 4];   al[mt][3] = Wlw[w0 + 292];
            }
            uint32_t bh[4][2], bl[4][2];
#pragma unroll
            for (int nt = 0; nt < 4; nt++) {
                int w0 = (warpN * 32 + nt * 8 + r) * 36 + kk * 8 + q;
                bh[nt][0] = Xhw[w0];  bh[nt][1] = Xhw[w0 + 4];
                bl[nt][0] = Xlw[w0];  bl[nt][1] = Xlw[w0 + 4];
            }
#pragma unroll
            for (int mt = 0; mt < 2; mt++)
#pragma unroll
                for (int nt = 0; nt < 4; nt++) {
                    mma16816(c[mt][nt], ah[mt], bh[nt]);
                    mma16816(c[mt][nt], ah[mt], bl[nt]);
                    mma16816(c[mt][nt], al[mt], bh[nt]);
                }
        }
    }

    // --- epilogue: write fp32 partials ---
#pragma unroll
    for (int mt = 0; mt < 2; mt++)
#pragma unroll
        for (int nt = 0; nt < 4; nt++) {
            int row = i0 + warpM * 32 + mt * 16 + r;
            int col = warpN * 32 + nt * 8 + 2 * q;
            *(float2*)(pout + (size_t)row * 64 + col) =
                make_float2(c[mt][nt][0], c[mt][nt][1]);
            *(float2*)(pout + (size_t)(row + 8) * 64 + col) =
                make_float2(c[mt][nt][2], c[mt][nt][3]);
        }
}

// ---------------------------------------------------------------------------
// K5: out = sum over NCHUNK partials (deterministic, no atomics).
// ---------------------------------------------------------------------------
__global__ void __launch_bounds__(256) k_final(float* __restrict__ out) {
    size_t idx4 = (size_t)blockIdx.x * 256 + threadIdx.x;
    const size_t N4 = (size_t)BB * TT * DD / 4;
    if (idx4 >= N4) return;
    const float4* p = (const float4*)g_partial;
    float4 a = p[idx4];
    float4 b = p[N4 + idx4];
    float4 c = p[2 * N4 + idx4];
    float4 d = p[3 * N4 + idx4];
    float4 o;
    o.x = (a.x + b.x) + (c.x + d.x);
    o.y = (a.y + b.y) + (c.y + d.y);
    o.z = (a.z + b.z) + (c.z + d.z);
    o.w = (a.w + b.w) + (c.w + d.w);
    ((float4*)out)[idx4] = o;
}

// ---------------------------------------------------------------------------
extern "C" void kernel_launch(void* const* d_in, const int* in_sizes, int n_in,
                              void* d_out, int out_size) {
    const float* x  = (const float*)d_in[0];
    const float* W1 = (const float*)d_in[1];
    const float* b1 = (const float*)d_in[2];
    const float* W2 = (const float*)d_in[3];
    const float* b2 = (const float*)d_in[4];
    float* out = (float*)d_out;

    static int smem_set = 0;
    if (!smem_set) {
        cudaFuncSetAttribute(k_scores, cudaFuncAttributeMaxDynamicSharedMemorySize,
                             64 * 128 * 2 * (int)sizeof(float));
        cudaFuncSetAttribute(k_out, cudaFuncAttributeMaxDynamicSharedMemorySize,
                             KOUT_SMEM_BYTES);
        smem_set = 1;
    }

    k_encode<<<BB * TT, 64>>>(x, W1, b1, W2, b2);
    k_scores<<<dim3(TT / 128, TT / 128, BB), 256,
               64 * 128 * 2 * sizeof(float)>>>(x);
    k_pstats_reduce<<<BB * TT / 8, 256>>>();
    k_out<<<dim3(TT / 128, NCHUNK, BB), 256, KOUT_SMEM_BYTES>>>(x);
    k_final<<<(BB * TT * DD / 4 + 255) / 256, 256>>>(out);
}

// round 14
// speedup vs baseline: 1.8060x; 1.1132x over previous
#include <cuda_runtime.h>
#include <cuda_bf16.h>
#include <math.h>
#include <stdint.h>

#define BB 4
#define TT 4096
#define DD 64
#define NCHUNK 4
#define JCHUNK (TT / NCHUNK)
#define NT2 64                // 64-column-granularity stat slots per row

// Scratch (device globals — allocation-free contract)
__device__ float  g_enc[(size_t)BB * TT * DD];              // 4 MB
__device__ float  g_scores[(size_t)BB * TT * TT];           // 268 MB
__device__ float2 g_pstats[(size_t)BB * TT * NT2];          // 8 MB
__device__ float2 g_stats[(size_t)BB * TT];                 // per row: {max, 1/Z}
__device__ float  g_partial[(size_t)NCHUNK * BB * TT * DD]; // 16 MB split-K partials

// ---- bf16 split helpers ----
__device__ __forceinline__ void bf16_split2(float v0, float v1,
                                            uint32_t& hi, uint32_t& lo) {
    __nv_bfloat16 h0 = __float2bfloat16(v0);
    __nv_bfloat16 h1 = __float2bfloat16(v1);
    float r0 = v0 - __bfloat162float(h0);
    float r1 = v1 - __bfloat162float(h1);
    __nv_bfloat162 hp; hp.x = h0; hp.y = h1;
    __nv_bfloat162 lp; lp.x = __float2bfloat16(r0); lp.y = __float2bfloat16(r1);
    hi = *(uint32_t*)&hp;
    lo = *(uint32_t*)&lp;
}

// mma.sync m16n8k16 row.col bf16 -> fp32 accumulate in place
__device__ __forceinline__ void mma16816(float* c, const uint32_t* a, const uint32_t* b) {
    asm volatile(
        "mma.sync.aligned.m16n8k16.row.col.f32.bf16.bf16.f32 "
        "{%0,%1,%2,%3}, {%4,%5,%6,%7}, {%8,%9}, {%0,%1,%2,%3};"
        : "+f"(c[0]), "+f"(c[1]), "+f"(c[2]), "+f"(c[3])
        : "r"(a[0]), "r"(a[1]), "r"(a[2]), "r"(a[3]), "r"(b[0]), "r"(b[1]));
}

// ---------------------------------------------------------------------------
// K1: encoded = tanh(softmax(x@W1 + b1) @ W2 + b2)   one 64-thread block/token
// ---------------------------------------------------------------------------
__global__ void k_encode(const float* __restrict__ x,
                         const float* __restrict__ W1, const float* __restrict__ b1,
                         const float* __restrict__ W2, const float* __restrict__ b2) {
    int token = blockIdx.x;
    int t = threadIdx.x;
    __shared__ float xs[64];
    __shared__ float red[64];
    __shared__ float hs[64];

    xs[t] = x[(size_t)token * 64 + t];
    __syncthreads();

    float acc = b1[t];
#pragma unroll
    for (int d = 0; d < 64; d++) acc = fmaf(xs[d], W1[d * 64 + t], acc);

    red[t] = acc; __syncthreads();
#pragma unroll
    for (int s = 32; s > 0; s >>= 1) {
        if (t < s) red[t] = fmaxf(red[t], red[t + s]);
        __syncthreads();
    }
    float m = red[0];
    __syncthreads();
    float e = expf(acc - m);
    red[t] = e; __syncthreads();
#pragma unroll
    for (int s = 32; s > 0; s >>= 1) {
        if (t < s) red[t] = red[t] + red[t + s];
        __syncthreads();
    }
    float h = e / red[0];
    hs[t] = h;
    __syncthreads();

    float acc2 = b2[t];
#pragma unroll
    for (int d = 0; d < 64; d++) acc2 = fmaf(hs[d], W2[d * 64 + t], acc2);

    g_enc[(size_t)token * 64 + t] = tanhf(acc2);
}

// ---------------------------------------------------------------------------
// K2: scores[b,i,j] = <x[b,i,:], enc[b,j,:]>  via mma bf16 hi/lo split.
// CTA 256 thr = 8 warps; tile 128(i) x 128(j), K=64 one-shot.
// Layouts [row][k-word] with stride 36 u32 => conflict-free fragment LDS
// (identical scheme verified in k_out R13).
// Also emits per-(row, 64-col-half) partial softmax stats.
// ---------------------------------------------------------------------------
#define KS_SMEM_BYTES (4 * 128 * 36 * 4)   // 73728

__global__ void __launch_bounds__(256) k_scores(const float* __restrict__ x) {
    extern __shared__ __align__(16) uint32_t sw[];
    uint32_t* Ahw = sw;                       // X hi   [128 i][36 w]
    uint32_t* Alw = Ahw + 128 * 36;           // X lo
    uint32_t* Bhw = Alw + 128 * 36;           // E hi   [128 j][36 w]
    uint32_t* Blw = Bhw + 128 * 36;           // E lo

    int bj = blockIdx.x, bi = blockIdx.y, b = blockIdx.z;
    int i0 = bi * 128, j0 = bj * 128;
    const float* xb = x + (size_t)b * TT * DD;
    const float* eb = g_enc + (size_t)b * TT * DD;

    int tid  = threadIdx.x;
    int lane = tid & 31;
    int wid  = tid >> 5;
    int warpM = wid & 3;          // 4 warps x 32 rows = 128 i
    int warpN = wid >> 2;         // 2 warps x 64 cols = 128 j
    int r = lane >> 2, q = lane & 3;

    // --- fill: row = tid>>1 (0..127), half = tid&1 covers d 32*half..+31 ---
    {
        int row  = tid >> 1;
        int half = tid & 1;
        const float* ax = xb + (size_t)(i0 + row) * 64 + half * 32;
        const float* be = eb + (size_t)(j0 + row) * 64 + half * 32;
        int wbase = row * 36 + half * 16;
#pragma unroll
        for (int it = 0; it < 8; it++) {
            float4 v = *(const float4*)(ax + it * 4);
            uint32_t h0, l0, h1, l1;
            bf16_split2(v.x, v.y, h0, l0);
            bf16_split2(v.z, v.w, h1, l1);
            Ahw[wbase + it * 2]     = h0;  Ahw[wbase + it * 2 + 1] = h1;
            Alw[wbase + it * 2]     = l0;  Alw[wbase + it * 2 + 1] = l1;
            float4 u = *(const float4*)(be + it * 4);
            bf16_split2(u.x, u.y, h0, l0);
            bf16_split2(u.z, u.w, h1, l1);
            Bhw[wbase + it * 2]     = h0;  Bhw[wbase + it * 2 + 1] = h1;
            Blw[wbase + it * 2]     = l0;  Blw[wbase + it * 2 + 1] = l1;
        }
    }
    __syncthreads();

    float c[2][8][4];
#pragma unroll
    for (int mt = 0; mt < 2; mt++)
#pragma unroll
        for (int nt = 0; nt < 8; nt++)
#pragma unroll
            for (int e = 0; e < 4; e++) c[mt][nt][e] = 0.0f;

    // --- MMA mainloop: K=64 -> 4 k-steps of 16 ---
#pragma unroll
    for (int kk = 0; kk < 4; kk++) {
        uint32_t ah[2][4], al[2][4];
#pragma unroll
        for (int mt = 0; mt < 2; mt++) {
            int w0 = (warpM * 32 + mt * 16 + r) * 36 + kk * 8 + q;
            ah[mt][0] = Ahw[w0];       ah[mt][1] = Ahw[w0 + 288];
            ah[mt][2] = Ahw[w0 + 4];   ah[mt][3] = Ahw[w0 + 292];
            al[mt][0] = Alw[w0];       al[mt][1] = Alw[w0 + 288];
            al[mt][2] = Alw[w0 + 4];   al[mt][3] = Alw[w0 + 292];
        }
        uint32_t bh[8][2], bl[8][2];
#pragma unroll
        for (int nt = 0; nt < 8; nt++) {
            int w0 = (warpN * 64 + nt * 8 + r) * 36 + kk * 8 + q;
            bh[nt][0] = Bhw[w0];  bh[nt][1] = Bhw[w0 + 4];
            bl[nt][0] = Blw[w0];  bl[nt][1] = Blw[w0 + 4];
        }
#pragma unroll
        for (int mt = 0; mt < 2; mt++)
#pragma unroll
            for (int nt = 0; nt < 8; nt++) {
                mma16816(c[mt][nt], ah[mt], bh[nt]);
                mma16816(c[mt][nt], ah[mt], bl[nt]);
                mma16816(c[mt][nt], al[mt], bh[nt]);
            }
    }

    // --- epilogue: write scores + per-(row, 64-col-half) softmax stats ---
    float* sb = g_scores + (size_t)b * TT * TT;
#pragma unroll
    for (int mt = 0; mt < 2; mt++) {
#pragma unroll
        for (int nt = 0; nt < 8; nt++) {
            int row = i0 + warpM * 32 + mt * 16 + r;
            int col = j0 + warpN * 64 + nt * 8 + 2 * q;
            *(float2*)(sb + (size_t)row * TT + col) =
                make_float2(c[mt][nt][0], c[mt][nt][1]);
            *(float2*)(sb + (size_t)(row + 8) * TT + col) =
                make_float2(c[mt][nt][2], c[mt][nt][3]);
        }
        // stats: rows (r) and (r+8) of this mt, over warpN's 64 columns
#pragma unroll
        for (int rs = 0; rs < 2; rs++) {
            float m = c[mt][0][rs * 2];
#pragma unroll
            for (int nt = 0; nt < 8; nt++) {
                m = fmaxf(m, c[mt][nt][rs * 2]);
                m = fmaxf(m, c[mt][nt][rs * 2 + 1]);
            }
            m = fmaxf(m, __shfl_xor_sync(0xffffffffu, m, 1));
            m = fmaxf(m, __shfl_xor_sync(0xffffffffu, m, 2));
            float z = 0.0f;
#pragma unroll
            for (int nt = 0; nt < 8; nt++) {
                z += __expf(c[mt][nt][rs * 2]     - m);
                z += __expf(c[mt][nt][rs * 2 + 1] - m);
            }
            z += __shfl_xor_sync(0xffffffffu, z, 1);
            z += __shfl_xor_sync(0xffffffffu, z, 2);
            if (q == 0) {
                int row = i0 + warpM * 32 + mt * 16 + r + rs * 8;
                g_pstats[((size_t)b * TT + row) * NT2 + bj * 2 + warpN] =
                    make_float2(m, z);
            }
        }
    }
}

// ---------------------------------------------------------------------------
// K3: reduce 64 per-half partials per row -> {max, 1/Z}. One warp per row.
// ---------------------------------------------------------------------------
__global__ void __launch_bounds__(256) k_pstats_reduce() {
    int row = blockIdx.x * 8 + (threadIdx.x >> 5);
    int lane = threadIdx.x & 31;
    const float2* pr = g_pstats + (size_t)row * NT2;
    float2 p0 = pr[lane];
    float2 p1 = pr[lane + 32];
    float m = fmaxf(p0.x, p1.x);
    float z = p0.y * __expf(p0.x - m) + p1.y * __expf(p1.x - m);
#pragma unroll
    for (int o = 16; o > 0; o >>= 1) {
        float mo = __shfl_xor_sync(0xffffffffu, m, o);
        float zo = __shfl_xor_sync(0xffffffffu, z, o);
        float mn = fmaxf(m, mo);
        z = z * __expf(m - mn) + zo * __expf(mo - mn);
        m = mn;
    }
    if (lane == 0) g_stats[row] = make_float2(m, 1.0f / z);
}

// ---------------------------------------------------------------------------
// K4: split-K partials of out[b,i,d] = sum_j w_j(i) x[b,j,d]
// Tensor-core mainloop (mma.sync m16n8k16 bf16, hi/lo split, fp32 acc).
// Unchanged from R13 (verified).
// ---------------------------------------------------------------------------
#define KOUT_SMEM_BYTES ((2 * 128 * 36 + 2 * 64 * 36) * 4)   // 55296

__global__ void __launch_bounds__(256) k_out(const float* __restrict__ x) {
    extern __shared__ __align__(16) uint32_t sw[];
    uint32_t* Whw = sw;                       // W hi  [128 i][36 w]
    uint32_t* Wlw = Whw + 128 * 36;           // W lo
    uint32_t* Xhw = Wlw + 128 * 36;           // X hi  [64 d][36 w]
    uint32_t* Xlw = Xhw + 64 * 36;            // X lo

    int bi = blockIdx.x, chunk = blockIdx.y, b = blockIdx.z;
    int i0 = bi * 128;
    const float*  xb  = x + (size_t)b * TT * DD;
    const float*  att = g_scores + (size_t)b * TT * TT;
    const float2* st  = g_stats + (size_t)b * TT;
    float* pout = g_partial + ((size_t)chunk * BB + b) * TT * DD;

    int tid  = threadIdx.x;
    int lane = tid & 31;
    int wid  = tid >> 5;
    int warpM = wid & 3;
    int warpN = wid >> 2;
    int r = lane >> 2, q = lane & 3;

    int jp = tid >> 3;
    int l8 = tid & 7;

    float c[2][4][4];
#pragma unroll
    for (int mt = 0; mt < 2; mt++)
#pragma unroll
        for (int nt = 0; nt < 4; nt++)
#pragma unroll
            for (int e = 0; e < 4; e++) c[mt][nt][e] = 0.0f;

    int jbeg = chunk * JCHUNK, jend = jbeg + JCHUNK;
    for (int j0 = jbeg; j0 < jend; j0 += 64) {
        __syncthreads();
        {
            int ja = j0 + 2 * jp;
            float2 s0 = st[ja], s1 = st[ja + 1];
            const float* a0 = att + (size_t)ja * TT + i0;
            const float* a1 = a0 + TT;
#pragma unroll
            for (int t = 0; t < 16; t++) {
                int i = l8 + 8 * t;
                float w0 = __expf(a0[i] - s0.x) * s0.y;
                float w1 = __expf(a1[i] - s1.x) * s1.y;
                uint32_t hi, lo;
                bf16_split2(w0, w1, hi, lo);
                Whw[i * 36 + jp] = hi;
                Wlw[i * 36 + jp] = lo;
            }
        }
        {
            const float* x0 = xb + (size_t)(j0 + 2 * jp) * 64;
            const float* x1 = x0 + 64;
#pragma unroll
            for (int t = 0; t < 8; t++) {
                int d = l8 + 8 * t;
                uint32_t hi, lo;
                bf16_split2(x0[d], x1[d], hi, lo);
                Xhw[d * 36 + jp] = hi;
                Xlw[d * 36 + jp] = lo;
            }
        }
        __syncthreads();

#pragma unroll
        for (int kk = 0; kk < 4; kk++) {
            uint32_t ah[2][4], al[2][4];
#pragma unroll
            for (int mt = 0; mt < 2; mt++) {
                int w0 = (warpM * 32 + mt * 16 + r) * 36 + kk * 8 + q;
                ah[mt][0] = Whw[w0];       ah[mt][1] = Whw[w0 + 288];
                ah[mt][2] = Whw[w0 + 4];   ah[mt][3] = Whw[w0 + 292];
                al[mt][0] = Wlw[w0];       al[mt][1] = Wlw[w0 + 288];
                al[mt][2] = Wlw[w0 + 4];   al[mt][3] = Wlw[w0 + 292];
            }
            uint32_t bh[4][2], bl[4][2];
#pragma unroll
            for (int nt = 0; nt < 4; nt++) {
                int w0 = (warpN * 32 + nt * 8 + r) * 36 + kk * 8 + q;
                bh[nt][0] = Xhw[w0];  bh[nt][1] = Xhw[w0 + 4];
                bl[nt][0] = Xlw[w0];  bl[nt][1] = Xlw[w0 + 4];
            }
#pragma unroll
            for (int mt = 0; mt < 2; mt++)
#pragma unroll
                for (int nt = 0; nt < 4; nt++) {
                    mma16816(c[mt][nt], ah[mt], bh[nt]);
                    mma16816(c[mt][nt], ah[mt], bl[nt]);
                    mma16816(c[mt][nt], al[mt], bh[nt]);
                }
        }
    }

#pragma unroll
    for (int mt = 0; mt < 2; mt++)
#pragma unroll
        for (int nt = 0; nt < 4; nt++) {
            int row = i0 + warpM * 32 + mt * 16 + r;
            int col = warpN * 32 + nt * 8 + 2 * q;
            *(float2*)(pout + (size_t)row * 64 + col) =
                make_float2(c[mt][nt][0], c[mt][nt][1]);
            *(float2*)(pout + (size_t)(row + 8) * 64 + col) =
                make_float2(c[mt][nt][2], c[mt][nt][3]);
        }
}

// ---------------------------------------------------------------------------
// K5: out = sum over NCHUNK partials (deterministic, no atomics).
// ---------------------------------------------------------------------------
__global__ void __launch_bounds__(256) k_final(float* __restrict__ out) {
    size_t idx4 = (size_t)blockIdx.x * 256 + threadIdx.x;
    const size_t N4 = (size_t)BB * TT * DD / 4;
    if (idx4 >= N4) return;
    const float4* p = (const float4*)g_partial;
    float4 a = p[idx4];
    float4 b = p[N4 + idx4];
    float4 c = p[2 * N4 + idx4];
    float4 d = p[3 * N4 + idx4];
    float4 o;
    o.x = (a.x + b.x) + (c.x + d.x);
    o.y = (a.y + b.y) + (c.y + d.y);
    o.z = (a.z + b.z) + (c.z + d.z);
    o.w = (a.w + b.w) + (c.w + d.w);
    ((float4*)out)[idx4] = o;
}

// ---------------------------------------------------------------------------
extern "C" void kernel_launch(void* const* d_in, const int* in_sizes, int n_in,
                              void* d_out, int out_size) {
    const float* x  = (const float*)d_in[0];
    const float* W1 = (const float*)d_in[1];
    const float* b1 = (const float*)d_in[2];
    const float* W2 = (const float*)d_in[3];
    const float* b2 = (const float*)d_in[4];
    float* out = (float*)d_out;

    static int smem_set = 0;
    if (!smem_set) {
        cudaFuncSetAttribute(k_scores, cudaFuncAttributeMaxDynamicSharedMemorySize,
                             KS_SMEM_BYTES);
        cudaFuncSetAttribute(k_out, cudaFuncAttributeMaxDynamicSharedMemorySize,
                             KOUT_SMEM_BYTES);
        smem_set = 1;
    }

    k_encode<<<BB * TT, 64>>>(x, W1, b1, W2, b2);
    k_scores<<<dim3(TT / 128, TT / 128, BB), 256, KS_SMEM_BYTES>>>(x);
    k_pstats_reduce<<<BB * TT / 8, 256>>>();
    k_out<<<dim3(TT / 128, NCHUNK, BB), 256, KOUT_SMEM_BYTES>>>(x);
    k_final<<<(BB * TT * DD / 4 + 255) / 256, 256>>>(out);
}